// round 11
// baseline (speedup 1.0000x reference)
#include <cuda_runtime.h>
#include <stdint.h>

// out[r, :] = sum over edges (r, c) of weight[c, :]
// adj: [2, nnz] (rows then cols), dtype int64 OR int32 (runtime-detected)
// weight: [size, 256] float32 ; out: [size, 256] float32
//
// R11: self-cleaning state kills the 5.5us init kernel. __device__ globals
// start zeroed; the gather kernel restores the all-zero invariant (bcount
// per-row, ovf/done via last-block protocol) before kernel_launch returns,
// so every call (and every graph replay) sees identical initial state.
// dtype detect is a per-block ballot inside fill (adj head is L2-hot).

#define OUTF 256
#define MAXN   (1 << 17)   // max rows   (problem: 100000)
#define MAXNNZ (1 << 17)   // max edges  (problem: 100000)
#define CAP 8              // bucket slots per row (Poisson(1): P(deg>8)~1e-7)

__device__ int g_bcount[MAXN];           // per-row edge count (zero invariant)
__device__ int g_slots[MAXN * CAP + 32]; // bucket storage (count-gated)
__device__ int2 g_ovf[MAXNNZ];           // exact overflow list
__device__ int g_ovf_count;              // zero invariant
__device__ unsigned g_done;              // zero invariant (last-block proto)

// ---------------------------------------------------------------- helpers
__device__ __forceinline__ int detect_is64(const void* adj, long long n,
                                           int n_check) {
    // Warp 0 of the calling block: int64 indices are all in [0, n);
    // int32-pairs read as int64 are out of range w.h.p. over 64 samples.
    const long long* a = (const long long*)adj;
    int ok = 1;
    for (int k = threadIdx.x; k < n_check; k += 32) {
        long long v = a[k];
        if (v < 0 || v >= n) ok = 0;
    }
    unsigned m = __ballot_sync(0xFFFFFFFFu, ok);
    return (m == 0xFFFFFFFFu) ? 1 : 0;
}

// --------------------------------------------------- K1: bucket fill
__global__ void __launch_bounds__(256)
fill_kernel(const void* __restrict__ adj, int n, int nnz, int n_check) {
    __shared__ int sh_is64;
    if (threadIdx.x < 32) {
        int is64 = detect_is64(adj, (long long)n, n_check);
        if (threadIdx.x == 0) sh_is64 = is64;
    }
    __syncthreads();
    const int is64 = sh_is64;

    int e = blockIdx.x * blockDim.x + threadIdx.x;
    int stride = gridDim.x * blockDim.x;
    if (is64) {
        const long long* a = (const long long*)adj;
        for (; e < nnz; e += stride) {
            int r = (int)a[e];
            int c = (int)a[nnz + e];
            int pos = atomicAdd(&g_bcount[r], 1);
            if (pos < CAP) g_slots[r * CAP + pos] = c;
            else { int o = atomicAdd(&g_ovf_count, 1); g_ovf[o] = make_int2(r, c); }
        }
    } else {
        const int* a = (const int*)adj;
        for (; e < nnz; e += stride) {
            int r = a[e];
            int c = a[nnz + e];
            int pos = atomicAdd(&g_bcount[r], 1);
            if (pos < CAP) g_slots[r * CAP + pos] = c;
            else { int o = atomicAdd(&g_ovf_count, 1); g_ovf[o] = make_int2(r, c); }
        }
    }
}

// --------------------------------------------------------- K2: gather
// One warp per row. Lanes 0..7 carry the row's bucket (one 32B wavefront);
// indices distributed by shfl; weight rows loaded in independent pairs.
// Also restores the zero-state invariant for the next launch.
__global__ void __launch_bounds__(256)
gather_kernel(const float* __restrict__ weight, float* __restrict__ out,
              int n) {
    const int row  = (blockIdx.x * 256 + threadIdx.x) >> 5;
    const int lane = threadIdx.x & 31;

    if (row < n) {
        const int cnt = __ldg(&g_bcount[row]);           // warp-uniform
        const int m = min(cnt, CAP);

        const float4* w = (const float4*)weight;         // 64 float4 per row
        float4 a0 = make_float4(0.f, 0.f, 0.f, 0.f);
        float4 a1 = make_float4(0.f, 0.f, 0.f, 0.f);

        if (m > 0) {
            const int slot = __ldg(&g_slots[row * CAP + (lane & (CAP - 1))]);
            int k = 0;
            for (; k + 2 <= m; k += 2) {                 // independent pair
                int ca = __shfl_sync(0xFFFFFFFFu, slot, k);
                int cb = __shfl_sync(0xFFFFFFFFu, slot, k + 1);
                const float4* pa = w + (size_t)ca * 64;
                const float4* pb = w + (size_t)cb * 64;
                float4 va0 = __ldg(pa + lane);
                float4 va1 = __ldg(pa + lane + 32);
                float4 vb0 = __ldg(pb + lane);
                float4 vb1 = __ldg(pb + lane + 32);
                a0.x += va0.x + vb0.x; a0.y += va0.y + vb0.y;
                a0.z += va0.z + vb0.z; a0.w += va0.w + vb0.w;
                a1.x += va1.x + vb1.x; a1.y += va1.y + vb1.y;
                a1.z += va1.z + vb1.z; a1.w += va1.w + vb1.w;
            }
            if (k < m) {
                int ca = __shfl_sync(0xFFFFFFFFu, slot, k);
                const float4* pa = w + (size_t)ca * 64;
                float4 va0 = __ldg(pa + lane);
                float4 va1 = __ldg(pa + lane + 32);
                a0.x += va0.x; a0.y += va0.y; a0.z += va0.z; a0.w += va0.w;
                a1.x += va1.x; a1.y += va1.y; a1.z += va1.z; a1.w += va1.w;
            }
        }

        // Overflow (deg > CAP): exact; essentially never taken for random data.
        if (cnt > CAP) {
            int novf = *(volatile int*)&g_ovf_count;
            for (int e = 0; e < novf; e++) {
                int2 rc = g_ovf[e];
                if (rc.x == row) {
                    const float4* p = w + (size_t)rc.y * 64;
                    float4 v0 = __ldg(p + lane);
                    float4 v1 = __ldg(p + lane + 32);
                    a0.x += v0.x; a0.y += v0.y; a0.z += v0.z; a0.w += v0.w;
                    a1.x += v1.x; a1.y += v1.y; a1.z += v1.z; a1.w += v1.w;
                }
            }
        }

        float4* o = (float4*)out + (size_t)row * 64;
        o[lane]      = a0;
        o[lane + 32] = a1;

        if (lane == 0) g_bcount[row] = 0;    // restore zero invariant
    }

    // Last-block-done: reset ovf/done counters after all blocks' overflow
    // reads are complete. All threads reach here (no early return above).
    __syncthreads();
    if (threadIdx.x == 0) {
        __threadfence();
        unsigned d = atomicAdd(&g_done, 1u);
        if (d == gridDim.x - 1) {
            g_ovf_count = 0;
            g_done = 0;
            __threadfence();
        }
    }
}

// --------------------------------------------- fallback (capacity exceed)
__device__ int g_fb_is64;
__global__ void fb_detect_kernel(const long long* __restrict__ adj,
                                 long long nrows, int n_check) {
    if (threadIdx.x < 32) {
        int ok = 1;
        for (int k = threadIdx.x; k < n_check; k += 32) {
            long long v = adj[k];
            if (v < 0 || v >= nrows) ok = 0;
        }
        unsigned m = __ballot_sync(0xFFFFFFFFu, ok);
        if (threadIdx.x == 0) g_fb_is64 = (m == 0xFFFFFFFFu) ? 1 : 0;
    }
}
__global__ void zero_kernel(float4* __restrict__ out, long long n4) {
    long long i = (long long)blockIdx.x * blockDim.x + threadIdx.x;
    long long stride = (long long)gridDim.x * blockDim.x;
    float4 z = make_float4(0.f, 0.f, 0.f, 0.f);
    for (; i < n4; i += stride) out[i] = z;
}
__global__ void __launch_bounds__(256)
scatter_kernel(const void* __restrict__ adj,
               const float* __restrict__ weight,
               float* __restrict__ out, int nnz) {
    int edge = blockIdx.x * 4 + (threadIdx.x >> 6);
    int t = threadIdx.x & 63;
    if (edge >= nnz) return;
    long long r, c;
    if (g_fb_is64) {
        const long long* a = (const long long*)adj;
        r = a[edge]; c = a[nnz + edge];
    } else {
        const int* a = (const int*)adj;
        r = a[edge]; c = a[nnz + edge];
    }
    float4 v = __ldg((const float4*)(weight + c * OUTF) + t);
    float* o = out + r * OUTF + (long long)t * 4;
    atomicAdd(o + 0, v.x);
    atomicAdd(o + 1, v.y);
    atomicAdd(o + 2, v.z);
    atomicAdd(o + 3, v.w);
}

extern "C" void kernel_launch(void* const* d_in, const int* in_sizes, int n_in,
                              void* d_out, int out_size) {
    const void* adj = d_in[0];
    const float* weight = (const float*)d_in[2];
    float* out = (float*)d_out;

    int nnz = in_sizes[0] / 2;
    int n = out_size / OUTF;
    int n_check = nnz < 64 ? nnz : 64;

    if (n <= MAXN && nnz <= MAXNNZ) {
        int fblocks = (nnz + 255) / 256;
        if (fblocks > 296) fblocks = 296;
        fill_kernel<<<fblocks, 256>>>(adj, n, nnz, n_check);
        int blocks = (n + 7) / 8;            // 8 warps (rows) per block
        gather_kernel<<<blocks, 256>>>(weight, out, n);
    } else {
        fb_detect_kernel<<<1, 32>>>((const long long*)adj, (long long)n,
                                    n_check);
        long long n4 = (long long)out_size / 4;
        int zblocks = (int)((n4 + 255) / 256);
        if (zblocks < 1) zblocks = 1;
        zero_kernel<<<zblocks, 256>>>((float4*)out, n4);
        int sblocks = (nnz + 3) / 4;
        if (sblocks < 1) sblocks = 1;
        scatter_kernel<<<sblocks, 256>>>(adj, weight, out, nnz);
    }
}

// round 12
// speedup vs baseline: 1.2975x; 1.2975x over previous
#include <cuda_runtime.h>
#include <stdint.h>

// out[r, :] = sum over edges (r, c) of weight[c, :]
// adj: [2, nnz] (rows then cols), dtype int64 OR int32 (runtime-detected)
// weight: [size, 256] float32 ; out: [size, 256] float32
//
// R12: self-cleaning WITHOUT the R11 poison. No init kernel (g_bcount reset
// by gather lane0; everything else is count-gated or stateless). No overflow
// counter / done-protocol / threadfence: two bucket tiers cover deg<=32, and
// the (astronomically rare) deg>32 row is handled exactly by rescanning adj.
// Slot load is unconditional again so cnt/slot L2 trips overlap (R11's
// m>0 gate serialized the chain and cost 14us).

#define OUTF 256
#define MAXN   (1 << 17)   // max rows   (problem: 100000)
#define MAXNNZ (1 << 17)   // max edges  (problem: 100000)
#define CAP 8              // tier-1 slots per row (one 32B wavefront)
#define T2  24             // tier-2 slots per row (deg<=32 total)

__device__ int g_bcount[MAXN];             // per-row count (zero invariant)
__device__ int g_slots[MAXN * CAP + 32];   // tier-1 (count-gated, no init)
__device__ int g_slots2[MAXN * T2];        // tier-2 (count-gated, no init)

// ---------------------------------------------------------------- helpers
__device__ __forceinline__ int detect_is64(const void* adj, long long n,
                                           int n_check) {
    // Warp 0 of the calling block: int64 indices are all in [0, n);
    // int32-pairs read as int64 are out of range w.h.p. over 64 samples.
    const long long* a = (const long long*)adj;
    int ok = 1;
    for (int k = threadIdx.x; k < n_check; k += 32) {
        long long v = a[k];
        if (v < 0 || v >= n) ok = 0;
    }
    unsigned m = __ballot_sync(0xFFFFFFFFu, ok);
    return (m == 0xFFFFFFFFu) ? 1 : 0;
}

// --------------------------------------------------- K1: bucket fill
__global__ void __launch_bounds__(256)
fill_kernel(const void* __restrict__ adj, int n, int nnz, int n_check) {
    __shared__ int sh_is64;
    if (threadIdx.x < 32) {
        int is64 = detect_is64(adj, (long long)n, n_check);
        if (threadIdx.x == 0) sh_is64 = is64;
    }
    __syncthreads();
    const int is64 = sh_is64;

    int e = blockIdx.x * blockDim.x + threadIdx.x;
    int stride = gridDim.x * blockDim.x;
    if (is64) {
        const long long* a = (const long long*)adj;
        for (; e < nnz; e += stride) {
            int r = (int)a[e];
            int c = (int)a[nnz + e];
            int pos = atomicAdd(&g_bcount[r], 1);
            if (pos < CAP)          g_slots[r * CAP + pos] = c;
            else if (pos < CAP + T2) g_slots2[r * T2 + (pos - CAP)] = c;
            // pos >= 32: dropped here; gather rescans adj for this row.
        }
    } else {
        const int* a = (const int*)adj;
        for (; e < nnz; e += stride) {
            int r = a[e];
            int c = a[nnz + e];
            int pos = atomicAdd(&g_bcount[r], 1);
            if (pos < CAP)          g_slots[r * CAP + pos] = c;
            else if (pos < CAP + T2) g_slots2[r * T2 + (pos - CAP)] = c;
        }
    }
}

// --------------------------------------------------------- K2: gather
// One warp per row. Lanes 0..7 carry the row's tier-1 bucket (one 32B
// wavefront, loaded UNCONDITIONALLY so it overlaps the count load);
// indices distributed by shfl; weight rows loaded in independent pairs.
__global__ void __launch_bounds__(256)
gather_kernel(const float* __restrict__ weight, float* __restrict__ out,
              const void* __restrict__ adj, int nnz, int n) {
    const int row  = (blockIdx.x * 256 + threadIdx.x) >> 5;
    const int lane = threadIdx.x & 31;
    if (row >= n) return;

    // Issue both L2 loads back-to-back; they overlap.
    const int cnt  = __ldg(&g_bcount[row]);                       // uniform
    const int slot = __ldg(&g_slots[row * CAP + (lane & (CAP - 1))]);

    const float4* w = (const float4*)weight;          // 64 float4 per row
    float4 a0 = make_float4(0.f, 0.f, 0.f, 0.f);
    float4 a1 = make_float4(0.f, 0.f, 0.f, 0.f);

    if (cnt <= CAP + T2) {                            // normal path
        const int m = min(cnt, CAP);
        int k = 0;
        for (; k + 2 <= m; k += 2) {                  // independent pair
            int ca = __shfl_sync(0xFFFFFFFFu, slot, k);
            int cb = __shfl_sync(0xFFFFFFFFu, slot, k + 1);
            const float4* pa = w + (size_t)ca * 64;
            const float4* pb = w + (size_t)cb * 64;
            float4 va0 = __ldg(pa + lane);
            float4 va1 = __ldg(pa + lane + 32);
            float4 vb0 = __ldg(pb + lane);
            float4 vb1 = __ldg(pb + lane + 32);
            a0.x += va0.x + vb0.x; a0.y += va0.y + vb0.y;
            a0.z += va0.z + vb0.z; a0.w += va0.w + vb0.w;
            a1.x += va1.x + vb1.x; a1.y += va1.y + vb1.y;
            a1.z += va1.z + vb1.z; a1.w += va1.w + vb1.w;
        }
        if (k < m) {
            int ca = __shfl_sync(0xFFFFFFFFu, slot, k);
            const float4* pa = w + (size_t)ca * 64;
            float4 va0 = __ldg(pa + lane);
            float4 va1 = __ldg(pa + lane + 32);
            a0.x += va0.x; a0.y += va0.y; a0.z += va0.z; a0.w += va0.w;
            a1.x += va1.x; a1.y += va1.y; a1.z += va1.z; a1.w += va1.w;
        }
        // tier-2 (rare: deg in (8, 32])
        for (int t = CAP; t < cnt; t++) {
            int c = __ldg(&g_slots2[row * T2 + (t - CAP)]);
            const float4* p = w + (size_t)c * 64;
            float4 v0 = __ldg(p + lane);
            float4 v1 = __ldg(p + lane + 32);
            a0.x += v0.x; a0.y += v0.y; a0.z += v0.z; a0.w += v0.w;
            a1.x += v1.x; a1.y += v1.y; a1.z += v1.z; a1.w += v1.w;
        }
    } else {
        // Adversarial row (deg > 32): exact stateless rescan of adj.
        // n <= MAXN < 2^31/8 so the int32 view test in fill decided is64;
        // recompute it cheaply here (adj head is L2-hot).
        int is64;
        {
            const long long* a = (const long long*)adj;
            long long v0 = a[0];
            is64 = (v0 >= 0 && v0 < (long long)n);
            // one sample suffices only w.h.p.; use warp ballot over 32:
            int ok = 1;
            for (int kk = lane; kk < min(64, nnz); kk += 32) {
                long long v = a[kk];
                if (v < 0 || v >= (long long)n) ok = 0;
            }
            unsigned mb = __ballot_sync(0xFFFFFFFFu, ok);
            is64 = (mb == 0xFFFFFFFFu) ? 1 : 0;
        }
        if (is64) {
            const long long* a = (const long long*)adj;
            for (int e = 0; e < nnz; e++) {
                if ((int)a[e] == row) {
                    const float4* p = w + (size_t)((int)a[nnz + e]) * 64;
                    float4 v0 = __ldg(p + lane);
                    float4 v1 = __ldg(p + lane + 32);
                    a0.x += v0.x; a0.y += v0.y; a0.z += v0.z; a0.w += v0.w;
                    a1.x += v1.x; a1.y += v1.y; a1.z += v1.z; a1.w += v1.w;
                }
            }
        } else {
            const int* a = (const int*)adj;
            for (int e = 0; e < nnz; e++) {
                if (a[e] == row) {
                    const float4* p = w + (size_t)a[nnz + e] * 64;
                    float4 v0 = __ldg(p + lane);
                    float4 v1 = __ldg(p + lane + 32);
                    a0.x += v0.x; a0.y += v0.y; a0.z += v0.z; a0.w += v0.w;
                    a1.x += v1.x; a1.y += v1.y; a1.z += v1.z; a1.w += v1.w;
                }
            }
        }
    }

    float4* o = (float4*)out + (size_t)row * 64;
    o[lane]      = a0;
    o[lane + 32] = a1;

    if (lane == 0) g_bcount[row] = 0;     // restore zero invariant (cheap)
}

// --------------------------------------------- fallback (capacity exceed)
__device__ int g_fb_is64;
__global__ void fb_detect_kernel(const long long* __restrict__ adj,
                                 long long nrows, int n_check) {
    if (threadIdx.x < 32) {
        int ok = 1;
        for (int k = threadIdx.x; k < n_check; k += 32) {
            long long v = adj[k];
            if (v < 0 || v >= nrows) ok = 0;
        }
        unsigned m = __ballot_sync(0xFFFFFFFFu, ok);
        if (threadIdx.x == 0) g_fb_is64 = (m == 0xFFFFFFFFu) ? 1 : 0;
    }
}
__global__ void zero_kernel(float4* __restrict__ out, long long n4) {
    long long i = (long long)blockIdx.x * blockDim.x + threadIdx.x;
    long long stride = (long long)gridDim.x * blockDim.x;
    float4 z = make_float4(0.f, 0.f, 0.f, 0.f);
    for (; i < n4; i += stride) out[i] = z;
}
__global__ void __launch_bounds__(256)
scatter_kernel(const void* __restrict__ adj,
               const float* __restrict__ weight,
               float* __restrict__ out, int nnz) {
    int edge = blockIdx.x * 4 + (threadIdx.x >> 6);
    int t = threadIdx.x & 63;
    if (edge >= nnz) return;
    long long r, c;
    if (g_fb_is64) {
        const long long* a = (const long long*)adj;
        r = a[edge]; c = a[nnz + edge];
    } else {
        const int* a = (const int*)adj;
        r = a[edge]; c = a[nnz + edge];
    }
    float4 v = __ldg((const float4*)(weight + c * OUTF) + t);
    float* o = out + r * OUTF + (long long)t * 4;
    atomicAdd(o + 0, v.x);
    atomicAdd(o + 1, v.y);
    atomicAdd(o + 2, v.z);
    atomicAdd(o + 3, v.w);
}

extern "C" void kernel_launch(void* const* d_in, const int* in_sizes, int n_in,
                              void* d_out, int out_size) {
    const void* adj = d_in[0];
    const float* weight = (const float*)d_in[2];
    float* out = (float*)d_out;

    int nnz = in_sizes[0] / 2;
    int n = out_size / OUTF;
    int n_check = nnz < 64 ? nnz : 64;

    if (n <= MAXN && nnz <= MAXNNZ) {
        int fblocks = (nnz + 255) / 256;
        if (fblocks > 296) fblocks = 296;
        fill_kernel<<<fblocks, 256>>>(adj, n, nnz, n_check);
        int blocks = (n + 7) / 8;            // 8 warps (rows) per block
        gather_kernel<<<blocks, 256>>>(weight, out, adj, nnz, n);
    } else {
        fb_detect_kernel<<<1, 32>>>((const long long*)adj, (long long)n,
                                    n_check);
        long long n4 = (long long)out_size / 4;
        int zblocks = (int)((n4 + 255) / 256);
        if (zblocks < 1) zblocks = 1;
        zero_kernel<<<zblocks, 256>>>((float4*)out, n4);
        int sblocks = (nnz + 3) / 4;
        if (sblocks < 1) sblocks = 1;
        scatter_kernel<<<sblocks, 256>>>(adj, weight, out, nnz);
    }
}

// round 13
// speedup vs baseline: 1.4277x; 1.1003x over previous
#include <cuda_runtime.h>
#include <stdint.h>

// out[r, :] = sum over edges (r, c) of weight[c, :]
// adj: [2, nnz] (rows then cols), dtype int64 OR int32 (runtime-detected)
// weight: [size, 256] float32 ; out: [size, 256] float32
//
// R13 = R12 + three gather changes:
//  1) 2 rows per warp, software-pipelined: next row's cnt/slot L2 loads
//     issue before the current row's weight traffic (hides the 234cy hop).
//  2) __launch_bounds__(256, 6): guarantee 6 blocks/SM (75% occ).
//  3) __stcs output stores (evict-first; out never re-read) so duplicate
//     weight-row reads can live in L2.

#define OUTF 256
#define MAXN   (1 << 17)   // max rows   (problem: 100000)
#define MAXNNZ (1 << 17)   // max edges  (problem: 100000)
#define CAP 8              // tier-1 slots per row (one 32B wavefront)
#define T2  24             // tier-2 slots per row (deg<=32 total)

__device__ int g_bcount[MAXN];             // per-row count (zero invariant)
__device__ int g_slots[MAXN * CAP + 32];   // tier-1 (count-gated, no init)
__device__ int g_slots2[MAXN * T2];        // tier-2 (count-gated, no init)

// ---------------------------------------------------------------- helpers
__device__ __forceinline__ int detect_is64(const void* adj, long long n,
                                           int n_check) {
    // Warp 0 of the calling block: int64 indices are all in [0, n);
    // int32-pairs read as int64 are out of range w.h.p. over 64 samples.
    const long long* a = (const long long*)adj;
    int ok = 1;
    for (int k = threadIdx.x; k < n_check; k += 32) {
        long long v = a[k];
        if (v < 0 || v >= n) ok = 0;
    }
    unsigned m = __ballot_sync(0xFFFFFFFFu, ok);
    return (m == 0xFFFFFFFFu) ? 1 : 0;
}

// --------------------------------------------------- K1: bucket fill
__global__ void __launch_bounds__(256)
fill_kernel(const void* __restrict__ adj, int n, int nnz, int n_check) {
    __shared__ int sh_is64;
    if (threadIdx.x < 32) {
        int is64 = detect_is64(adj, (long long)n, n_check);
        if (threadIdx.x == 0) sh_is64 = is64;
    }
    __syncthreads();
    const int is64 = sh_is64;

    int e = blockIdx.x * blockDim.x + threadIdx.x;
    int stride = gridDim.x * blockDim.x;
    if (is64) {
        const long long* a = (const long long*)adj;
        for (; e < nnz; e += stride) {
            int r = (int)a[e];
            int c = (int)a[nnz + e];
            int pos = atomicAdd(&g_bcount[r], 1);
            if (pos < CAP)           g_slots[r * CAP + pos] = c;
            else if (pos < CAP + T2) g_slots2[r * T2 + (pos - CAP)] = c;
            // pos >= 32: dropped; gather rescans adj for this row (exact).
        }
    } else {
        const int* a = (const int*)adj;
        for (; e < nnz; e += stride) {
            int r = a[e];
            int c = a[nnz + e];
            int pos = atomicAdd(&g_bcount[r], 1);
            if (pos < CAP)           g_slots[r * CAP + pos] = c;
            else if (pos < CAP + T2) g_slots2[r * T2 + (pos - CAP)] = c;
        }
    }
}

// ------------------------------------------------ gather: one-row body
__device__ __forceinline__ void gather_row(
    const float4* __restrict__ w, float* __restrict__ out,
    const void* __restrict__ adj, int nnz, int n,
    int row, int cnt, int slot, int lane)
{
    float4 a0 = make_float4(0.f, 0.f, 0.f, 0.f);
    float4 a1 = make_float4(0.f, 0.f, 0.f, 0.f);

    if (cnt <= CAP + T2) {                            // normal path
        const int m = min(cnt, CAP);
        int k = 0;
        for (; k + 2 <= m; k += 2) {                  // independent pair
            int ca = __shfl_sync(0xFFFFFFFFu, slot, k);
            int cb = __shfl_sync(0xFFFFFFFFu, slot, k + 1);
            const float4* pa = w + (size_t)ca * 64;
            const float4* pb = w + (size_t)cb * 64;
            float4 va0 = __ldg(pa + lane);
            float4 va1 = __ldg(pa + lane + 32);
            float4 vb0 = __ldg(pb + lane);
            float4 vb1 = __ldg(pb + lane + 32);
            a0.x += va0.x + vb0.x; a0.y += va0.y + vb0.y;
            a0.z += va0.z + vb0.z; a0.w += va0.w + vb0.w;
            a1.x += va1.x + vb1.x; a1.y += va1.y + vb1.y;
            a1.z += va1.z + vb1.z; a1.w += va1.w + vb1.w;
        }
        if (k < m) {
            int ca = __shfl_sync(0xFFFFFFFFu, slot, k);
            const float4* pa = w + (size_t)ca * 64;
            float4 va0 = __ldg(pa + lane);
            float4 va1 = __ldg(pa + lane + 32);
            a0.x += va0.x; a0.y += va0.y; a0.z += va0.z; a0.w += va0.w;
            a1.x += va1.x; a1.y += va1.y; a1.z += va1.z; a1.w += va1.w;
        }
        for (int t = CAP; t < cnt; t++) {             // tier-2 (rare)
            int c = __ldg(&g_slots2[row * T2 + (t - CAP)]);
            const float4* p = w + (size_t)c * 64;
            float4 v0 = __ldg(p + lane);
            float4 v1 = __ldg(p + lane + 32);
            a0.x += v0.x; a0.y += v0.y; a0.z += v0.z; a0.w += v0.w;
            a1.x += v1.x; a1.y += v1.y; a1.z += v1.z; a1.w += v1.w;
        }
    } else {
        // Adversarial row (deg > 32): exact stateless rescan of adj.
        int is64;
        {
            const long long* a = (const long long*)adj;
            int ok = 1;
            for (int kk = lane; kk < min(64, nnz); kk += 32) {
                long long v = a[kk];
                if (v < 0 || v >= (long long)n) ok = 0;
            }
            unsigned mb = __ballot_sync(0xFFFFFFFFu, ok);
            is64 = (mb == 0xFFFFFFFFu) ? 1 : 0;
        }
        if (is64) {
            const long long* a = (const long long*)adj;
            for (int e = 0; e < nnz; e++) {
                if ((int)a[e] == row) {
                    const float4* p = w + (size_t)((int)a[nnz + e]) * 64;
                    float4 v0 = __ldg(p + lane);
                    float4 v1 = __ldg(p + lane + 32);
                    a0.x += v0.x; a0.y += v0.y; a0.z += v0.z; a0.w += v0.w;
                    a1.x += v1.x; a1.y += v1.y; a1.z += v1.z; a1.w += v1.w;
                }
            }
        } else {
            const int* a = (const int*)adj;
            for (int e = 0; e < nnz; e++) {
                if (a[e] == row) {
                    const float4* p = w + (size_t)a[nnz + e] * 64;
                    float4 v0 = __ldg(p + lane);
                    float4 v1 = __ldg(p + lane + 32);
                    a0.x += v0.x; a0.y += v0.y; a0.z += v0.z; a0.w += v0.w;
                    a1.x += v1.x; a1.y += v1.y; a1.z += v1.z; a1.w += v1.w;
                }
            }
        }
    }

    float4* o = (float4*)out + (size_t)row * 64;
    __stcs(o + lane, a0);          // evict-first: out never re-read,
    __stcs(o + lane + 32, a1);     // keep L2 for duplicate weight rows
    if (lane == 0) g_bcount[row] = 0;   // restore zero invariant
}

// --------------------------------------------------------- K2: gather
// 2 rows per warp, software-pipelined: next row's cnt/slot issue before
// this row's weight traffic. 6 blocks/SM pinned.
__global__ void __launch_bounds__(256, 6)
gather_kernel(const float* __restrict__ weight, float* __restrict__ out,
              const void* __restrict__ adj, int nnz, int n) {
    const int lane   = threadIdx.x & 31;
    const int warp   = (blockIdx.x * 256 + threadIdx.x) >> 5;
    const int nwarps = gridDim.x * 8;
    const float4* w  = (const float4*)weight;

    int row = warp;
    if (row >= n) return;

    // prologue: fetch row 0's metadata
    int cnt  = __ldg(&g_bcount[row]);
    int slot = __ldg(&g_slots[row * CAP + (lane & (CAP - 1))]);

    while (true) {
        int nrow = row + nwarps;
        int ncnt = 0, nslot = 0;
        if (nrow < n) {                 // prefetch next row's metadata NOW
            ncnt  = __ldg(&g_bcount[nrow]);
            nslot = __ldg(&g_slots[nrow * CAP + (lane & (CAP - 1))]);
        }

        gather_row(w, out, adj, nnz, n, row, cnt, slot, lane);

        if (nrow >= n) break;
        row = nrow; cnt = ncnt; slot = nslot;
    }
}

// --------------------------------------------- fallback (capacity exceed)
__device__ int g_fb_is64;
__global__ void fb_detect_kernel(const long long* __restrict__ adj,
                                 long long nrows, int n_check) {
    if (threadIdx.x < 32) {
        int ok = 1;
        for (int k = threadIdx.x; k < n_check; k += 32) {
            long long v = adj[k];
            if (v < 0 || v >= nrows) ok = 0;
        }
        unsigned m = __ballot_sync(0xFFFFFFFFu, ok);
        if (threadIdx.x == 0) g_fb_is64 = (m == 0xFFFFFFFFu) ? 1 : 0;
    }
}
__global__ void zero_kernel(float4* __restrict__ out, long long n4) {
    long long i = (long long)blockIdx.x * blockDim.x + threadIdx.x;
    long long stride = (long long)gridDim.x * blockDim.x;
    float4 z = make_float4(0.f, 0.f, 0.f, 0.f);
    for (; i < n4; i += stride) out[i] = z;
}
__global__ void __launch_bounds__(256)
scatter_kernel(const void* __restrict__ adj,
               const float* __restrict__ weight,
               float* __restrict__ out, int nnz) {
    int edge = blockIdx.x * 4 + (threadIdx.x >> 6);
    int t = threadIdx.x & 63;
    if (edge >= nnz) return;
    long long r, c;
    if (g_fb_is64) {
        const long long* a = (const long long*)adj;
        r = a[edge]; c = a[nnz + edge];
    } else {
        const int* a = (const int*)adj;
        r = a[edge]; c = a[nnz + edge];
    }
    float4 v = __ldg((const float4*)(weight + c * OUTF) + t);
    float* o = out + r * OUTF + (long long)t * 4;
    atomicAdd(o + 0, v.x);
    atomicAdd(o + 1, v.y);
    atomicAdd(o + 2, v.z);
    atomicAdd(o + 3, v.w);
}

extern "C" void kernel_launch(void* const* d_in, const int* in_sizes, int n_in,
                              void* d_out, int out_size) {
    const void* adj = d_in[0];
    const float* weight = (const float*)d_in[2];
    float* out = (float*)d_out;

    int nnz = in_sizes[0] / 2;
    int n = out_size / OUTF;
    int n_check = nnz < 64 ? nnz : 64;

    if (n <= MAXN && nnz <= MAXNNZ) {
        int fblocks = (nnz + 255) / 256;
        if (fblocks > 296) fblocks = 296;
        fill_kernel<<<fblocks, 256>>>(adj, n, nnz, n_check);
        // 2 rows per warp: warps = ceil(n/2), 8 warps per block
        int warps = (n + 1) / 2;
        int blocks = (warps + 7) / 8;
        gather_kernel<<<blocks, 256>>>(weight, out, adj, nnz, n);
    } else {
        fb_detect_kernel<<<1, 32>>>((const long long*)adj, (long long)n,
                                    n_check);
        long long n4 = (long long)out_size / 4;
        int zblocks = (int)((n4 + 255) / 256);
        if (zblocks < 1) zblocks = 1;
        zero_kernel<<<zblocks, 256>>>((float4*)out, n4);
        int sblocks = (nnz + 3) / 4;
        if (sblocks < 1) sblocks = 1;
        scatter_kernel<<<sblocks, 256>>>(adj, weight, out, nnz);
    }
}